// round 5
// baseline (speedup 1.0000x reference)
#include <cuda_runtime.h>
#include <stdint.h>

#define BLOCK 256
#define SEG 8
#define CHUNK (BLOCK * SEG)          // 2048
#define MAXN (1 << 22)
#define MAXCH (MAXN / CHUNK)
#define BLOCKS_PER_SM 5
#define GRID (BLOCKS_PER_SM * 148)   // 740: exact wave-1 co-residency

#define GAMMA_F 0.99f
#define LAMBDA_F 0.95f
#define CLIP_EPS_F 0.2f

// ---- device scratch ----
__device__ float  g_adv[MAXN];
__device__ volatile float g_aggC[MAXCH];
__device__ volatile float g_aggD[MAXCH];
__device__ volatile float g_incv[MAXCH];
__device__ volatile int   g_aggFlag[MAXCH];
__device__ volatile int   g_incFlag[MAXCH];
__device__ int    g_ticket;
__device__ int    g_done;
__device__ double g_sum;
__device__ double g_sumsq;
__device__ int    g_boolByteLayout;

// ---- init: reset state + detect bool layout ----
__global__ void init_kernel(const uint8_t* __restrict__ t1,
                            const uint8_t* __restrict__ t2,
                            int n, int numChunks) {
    int i = blockIdx.x * blockDim.x + threadIdx.x;
    if (i < numChunks) { g_aggFlag[i] = 0; g_incFlag[i] = 0; }
    if (i == 0) { g_ticket = 0; g_done = 0; g_sum = 0.0; g_sumsq = 0.0; }
    if (blockIdx.x == 0) {
        __shared__ int found;
        if (threadIdx.x == 0) found = 0;
        __syncthreads();
        int limit16 = (n < 16384 ? n : 16384) / 16;
        const uint4* a = (const uint4*)t1;
        const uint4* b = (const uint4*)t2;
        unsigned acc = 0;
        for (int k = threadIdx.x; k < limit16; k += blockDim.x) {
            uint4 x = a[k], y = b[k];
            acc |= (x.x | x.y | x.z | x.w | y.x | y.y | y.z | y.w) & 0xFFFFFF00u;
        }
        if (acc) found = 1;
        __syncthreads();
        if (threadIdx.x == 0) g_boolByteLayout = found;
    }
}

__device__ __forceinline__ void ppo_row(float a, float v, float lp, float olp,
                                        float mean, float rinv, float* o) {
    float an = (a - mean) * rinv;
    float lr = a + v;
    float ratio = __expf(lp - olp);
    float cl = fminf(fmaxf(ratio, 1.f - CLIP_EPS_F), 1.f + CLIP_EPS_F);
    float loss = -fminf(ratio * an, cl * an);
    o[0] = an; o[1] = lr; o[2] = loss;
}

// ---- fused persistent kernel ----
__global__ __launch_bounds__(BLOCK, BLOCKS_PER_SM)
void fused_kernel(const float* __restrict__ rewards,
                  const float* __restrict__ values,
                  const float* __restrict__ next_values,
                  const float* __restrict__ log_probs,
                  const float* __restrict__ old_log_probs,
                  const void* __restrict__ terminated_raw,
                  const void* __restrict__ truncated_raw,
                  float* __restrict__ out,
                  int n, int numChunks)
{
    __shared__ float  s_aggC[BLOCK / 32];
    __shared__ float  s_aggD[BLOCK / 32];
    __shared__ float  s_incoming;
    __shared__ int    s_chunk;
    __shared__ float  s_mean, s_rinv;
    __shared__ double s_wsum[BLOCK / 32];
    __shared__ double s_wsq[BLOCK / 32];

    const int t = threadIdx.x;
    const int lane = t & 31;
    const int wrp  = t >> 5;
    const int byteLayout = g_boolByteLayout;
    const float GL = GAMMA_F * LAMBDA_F;

    float accSum = 0.f, accSq = 0.f;

    // ===== phase 1: reverse scan over chunks (dynamic tickets) =====
    for (;;) {
        if (t == 0) {
            int tk = atomicAdd(&g_ticket, 1);
            s_chunk = (tk < numChunks) ? (numChunks - 1 - tk) : -1;
        }
        __syncthreads();
        const int chunk = s_chunk;
        if (chunk < 0) break;
        const long long base = (long long)chunk * CHUNK + (long long)t * SEG;

        float cc[SEG], dd[SEG];
        const bool full = (base + SEG <= (long long)n);
        if (full) {
            float rr[SEG], vv[SEG], nn[SEG];
            *(float4*)(rr)     = __ldg((const float4*)(rewards + base));
            *(float4*)(rr + 4) = __ldg((const float4*)(rewards + base) + 1);
            *(float4*)(vv)     = __ldg((const float4*)(values + base));
            *(float4*)(vv + 4) = __ldg((const float4*)(values + base) + 1);
            *(float4*)(nn)     = __ldg((const float4*)(next_values + base));
            *(float4*)(nn + 4) = __ldg((const float4*)(next_values + base) + 1);

            int te8[SEG], tu8[SEG];
            if (byteLayout) {
                unsigned long long tm = *(const unsigned long long*)((const uint8_t*)terminated_raw + base);
                unsigned long long tr = *(const unsigned long long*)((const uint8_t*)truncated_raw + base);
#pragma unroll
                for (int j = 0; j < SEG; j++) {
                    te8[j] = (int)((tm >> (8 * j)) & 0xFFull);
                    tu8[j] = (int)((tr >> (8 * j)) & 0xFFull);
                }
            } else {
                const int4* tm4 = (const int4*)((const int*)terminated_raw + base);
                const int4* tr4 = (const int4*)((const int*)truncated_raw + base);
                int4 a0 = __ldg(tm4), a1 = __ldg(tm4 + 1);
                int4 b0 = __ldg(tr4), b1 = __ldg(tr4 + 1);
                te8[0]=a0.x; te8[1]=a0.y; te8[2]=a0.z; te8[3]=a0.w;
                te8[4]=a1.x; te8[5]=a1.y; te8[6]=a1.z; te8[7]=a1.w;
                tu8[0]=b0.x; tu8[1]=b0.y; tu8[2]=b0.z; tu8[3]=b0.w;
                tu8[4]=b1.x; tu8[5]=b1.y; tu8[6]=b1.z; tu8[7]=b1.w;
            }
#pragma unroll
            for (int j = 0; j < SEG; j++) {
                bool te = te8[j] != 0;
                bool tu = tu8[j] != 0;
                float nt = te ? 0.f : 1.f;
                dd[j] = rr[j] + GAMMA_F * nt * nn[j] - vv[j];
                cc[j] = (te || tu) ? 0.f : GL;
            }
        } else {
#pragma unroll
            for (int j = 0; j < SEG; j++) {
                long long idx = base + j;
                if (idx < (long long)n) {
                    bool te, tu;
                    if (byteLayout) {
                        te = ((const uint8_t*)terminated_raw)[idx] != 0;
                        tu = ((const uint8_t*)truncated_raw)[idx] != 0;
                    } else {
                        te = ((const int*)terminated_raw)[idx] != 0;
                        tu = ((const int*)truncated_raw)[idx] != 0;
                    }
                    float nt = te ? 0.f : 1.f;
                    dd[j] = rewards[idx] + GAMMA_F * nt * next_values[idx] - values[idx];
                    cc[j] = (te || tu) ? 0.f : GL;
                } else { cc[j] = 1.f; dd[j] = 0.f; }
            }
        }

        // per-thread segment composition
        float C = 1.f, D = 0.f;
#pragma unroll
        for (int j = SEG - 1; j >= 0; j--) { D = cc[j] * D + dd[j]; C = cc[j] * C; }

        // warp-level inclusive suffix scan via shuffles
        float iC = C, iD = D;
#pragma unroll
        for (int off = 1; off < 32; off <<= 1) {
            float oc = __shfl_down_sync(0xFFFFFFFFu, iC, off);
            float od = __shfl_down_sync(0xFFFFFFFFu, iD, off);
            float nD = fmaf(iC, od, iD);
            float nC = iC * oc;
            if (lane + off < 32) { iC = nC; iD = nD; }
        }
        float eC = __shfl_down_sync(0xFFFFFFFFu, iC, 1);
        float eD = __shfl_down_sync(0xFFFFFFFFu, iD, 1);
        if (lane == 31) { eC = 1.f; eD = 0.f; }

        if (lane == 0) { s_aggC[wrp] = iC; s_aggD[wrp] = iD; }
        __syncthreads();

        if (t == 0) {
            float bC = 1.f, bD = 0.f;
#pragma unroll
            for (int j = (BLOCK / 32) - 1; j >= 0; j--) {
                bD = fmaf(s_aggC[j], bD, s_aggD[j]);
                bC = s_aggC[j] * bC;
            }
            // publish aggregate: volatile stores + fence, NO atomic RMW
            g_aggC[chunk] = bC; g_aggD[chunk] = bD;
            __threadfence();
            g_aggFlag[chunk] = 1;
            if (bC == 0.f) {
                g_incv[chunk] = bD;
                __threadfence();
                g_incFlag[chunk] = 1;
            }
            float incoming = 0.f;
            if (chunk < numChunks - 1) {
                float aC = 1.f, aD = 0.f;
                int j = chunk + 1;
                for (;;) {
                    if (g_incFlag[j] != 0) {           // volatile read poll
                        __threadfence();
                        incoming = aC * g_incv[j] + aD;
                        break;
                    }
                    if (g_aggFlag[j] != 0) {           // volatile read poll
                        __threadfence();
                        float jc = g_aggC[j];
                        float jd = g_aggD[j];
                        aD = aC * jd + aD;
                        aC = aC * jc;
                        if (aC == 0.f || j == numChunks - 1) { incoming = aD; break; }
                        j++;
                    }
                }
            }
            if (bC != 0.f) {
                g_incv[chunk] = bC * incoming + bD;
                __threadfence();
                g_incFlag[chunk] = 1;
            }
            s_incoming = incoming;
        }
        __syncthreads();

        float win = s_incoming;
        for (int j = (BLOCK / 32) - 1; j > wrp; j--)
            win = fmaf(s_aggC[j], win, s_aggD[j]);

        float x = fmaf(eC, win, eD);
        if (full) {
            float outv[SEG];
#pragma unroll
            for (int j = SEG - 1; j >= 0; j--) {
                x = fmaf(cc[j], x, dd[j]);
                outv[j] = x;
                accSum += x; accSq = fmaf(x, x, accSq);
            }
            *(float4*)(g_adv + base)     = make_float4(outv[0], outv[1], outv[2], outv[3]);
            *(float4*)(g_adv + base + 4) = make_float4(outv[4], outv[5], outv[6], outv[7]);
        } else {
#pragma unroll
            for (int j = SEG - 1; j >= 0; j--) {
                x = fmaf(cc[j], x, dd[j]);
                long long idx = base + j;
                if (idx < (long long)n) {
                    g_adv[idx] = x;
                    accSum += x; accSq = fmaf(x, x, accSq);
                }
            }
        }
    }

    // block reduce sums -> global atomics (one-shot, fine)
    {
        double ds = (double)accSum, dq = (double)accSq;
#pragma unroll
        for (int o = 16; o > 0; o >>= 1) {
            ds += __shfl_down_sync(0xFFFFFFFFu, ds, o);
            dq += __shfl_down_sync(0xFFFFFFFFu, dq, o);
        }
        if (lane == 0) { s_wsum[wrp] = ds; s_wsq[wrp] = dq; }
        __syncthreads();
        if (t == 0) {
            double ts = 0.0, tq = 0.0;
#pragma unroll
            for (int w = 0; w < BLOCK / 32; w++) { ts += s_wsum[w]; tq += s_wsq[w]; }
            atomicAdd(&g_sum, ts);
            atomicAdd(&g_sumsq, tq);
        }
    }

    // ===== grid barrier: one atomic arrival, VOLATILE-LOAD polling =====
    __threadfence();
    if (t == 0) {
        atomicAdd(&g_done, 1);                     // single arrival RMW
        volatile int* vd = &g_done;
        int spins = 0;
        while (*vd < GRID) {                       // plain L2 read poll
            if (++spins > 4) __nanosleep(256);
        }
        __threadfence();
        double s = g_sum, q = g_sumsq;
        double mean = s / (double)n;
        double var = (q - s * s / (double)n) / (double)(n - 1);
        if (var < 0.0) var = 0.0;
        s_mean = (float)mean;
        s_rinv = (float)(1.0 / (sqrt(var) + 1e-9));
    }
    __syncthreads();
    const float mean = s_mean, rinv = s_rinv;

    // ===== phase 2: epilogue =====
    const long long nv4 = n / 4;
    const long long stride = (long long)GRID * BLOCK;
    for (long long i4 = (long long)blockIdx.x * BLOCK + t; i4 < nv4; i4 += stride) {
        long long b4 = i4 * 4;
        float4 a   = *(const float4*)(g_adv + b4);
        float4 v   = __ldcs((const float4*)(values + b4));
        float4 lp  = __ldcs((const float4*)(log_probs + b4));
        float4 olp = __ldcs((const float4*)(old_log_probs + b4));
        float o[12];
        ppo_row(a.x, v.x, lp.x, olp.x, mean, rinv, o + 0);
        ppo_row(a.y, v.y, lp.y, olp.y, mean, rinv, o + 3);
        ppo_row(a.z, v.z, lp.z, olp.z, mean, rinv, o + 6);
        ppo_row(a.w, v.w, lp.w, olp.w, mean, rinv, o + 9);
        float4* dst = (float4*)(out + b4 * 3);
        __stcs(dst + 0, make_float4(o[0], o[1], o[2],  o[3]));
        __stcs(dst + 1, make_float4(o[4], o[5], o[6],  o[7]));
        __stcs(dst + 2, make_float4(o[8], o[9], o[10], o[11]));
    }
    if (blockIdx.x == 0 && t == 0) {
        for (long long i = nv4 * 4; i < (long long)n; i++) {
            float o[3];
            ppo_row(g_adv[i], values[i], log_probs[i], old_log_probs[i], mean, rinv, o);
            out[i * 3 + 0] = o[0];
            out[i * 3 + 1] = o[1];
            out[i * 3 + 2] = o[2];
        }
    }
}

extern "C" void kernel_launch(void* const* d_in, const int* in_sizes, int n_in,
                              void* d_out, int out_size) {
    const float* rewards       = (const float*)d_in[0];
    const float* values        = (const float*)d_in[1];
    const float* next_values   = (const float*)d_in[2];
    const float* log_probs     = (const float*)d_in[3];
    const float* old_log_probs = (const float*)d_in[4];
    const void*  terminated    = d_in[5];
    const void*  truncated     = d_in[6];
    float* out = (float*)d_out;

    int n = in_sizes[0];
    int numChunks = (n + CHUNK - 1) / CHUNK;

    init_kernel<<<(numChunks + 255) / 256, 256>>>((const uint8_t*)terminated,
                                                  (const uint8_t*)truncated, n, numChunks);
    fused_kernel<<<GRID, BLOCK>>>(rewards, values, next_values,
                                  log_probs, old_log_probs,
                                  terminated, truncated, out, n, numChunks);
}

// round 6
// speedup vs baseline: 1.1294x; 1.1294x over previous
#include <cuda_runtime.h>
#include <stdint.h>

#define BLOCK 256
#define SEG 4
#define CHUNK (BLOCK * SEG)          // 1024
#define CPR 3                        // chunks per region
#define BLOCKS_PER_SM 5
#define GRID (BLOCKS_PER_SM * 148)   // 740 co-resident
#define HALO 256

#define GAMMA_F 0.99f
#define LAMBDA_F 0.95f
#define CLIP_EPS_F 0.2f

// ---- device scratch (zero-initialized at load; self-resetting) ----
__device__ float  g_adv[1 << 22];
__device__ double g_psum[GRID];
__device__ double g_psq[GRID];
__device__ int    g_done;
__device__ int    g_done2;

__device__ __forceinline__ void ppo_row(float a, float v, float lp, float olp,
                                        float mean, float rinv, float* o) {
    float an = (a - mean) * rinv;
    float lr = a + v;
    float ratio = __expf(lp - olp);
    float cl = fminf(fmaxf(ratio, 1.f - CLIP_EPS_F), 1.f + CLIP_EPS_F);
    float loss = -fminf(ratio * an, cl * an);
    o[0] = an; o[1] = lr; o[2] = loss;
}

__global__ __launch_bounds__(BLOCK, BLOCKS_PER_SM)
void fused_kernel(const float* __restrict__ rewards,
                  const float* __restrict__ values,
                  const float* __restrict__ next_values,
                  const float* __restrict__ log_probs,
                  const float* __restrict__ old_log_probs,
                  const void* __restrict__ term_raw,
                  const void* __restrict__ trun_raw,
                  float* __restrict__ out,
                  int n, int numChunks, int numRegions)
{
    __shared__ float  s_aggC[BLOCK / 32];
    __shared__ float  s_aggD[BLOCK / 32];
    __shared__ float  s_seed[2];
    __shared__ float  s_mean, s_rinv;
    __shared__ double s_wsum[BLOCK / 32];
    __shared__ double s_wsq[BLOCK / 32];

    const int t = threadIdx.x;
    const int lane = t & 31;
    const int wrp  = t >> 5;
    const float GL = GAMMA_F * LAMBDA_F;

    // ---- per-block bool-layout detection (first 1KB of each array) ----
    int pred = 0;
    if (t < 64 && n >= 1024) {
        uint4 x = __ldg((const uint4*)term_raw + t);
        uint4 y = __ldg((const uint4*)trun_raw + t);
        pred = ((x.x | x.y | x.z | x.w | y.x | y.y | y.z | y.w) & 0xFFFFFF00u) != 0;
    }
    const int byteLayout = __syncthreads_or(pred);

    float accSum = 0.f, accSq = 0.f;

    // ===== phase 1: independent regions, local right-to-left scan =====
    for (int r = blockIdx.x; r < numRegions; r += GRID) {
        const int cBeg = r * CPR;
        const int cEnd = min(cBeg + CPR, numChunks);
        const long long endElem = (long long)cEnd * CHUNK;

        // --- halo: warp 7 computes seed = adv value at element endElem ---
        if (wrp == 7) {
            float hC = 1.f, hD = 0.f;
            if (endElem < (long long)n) {
                const long long hb = endElem + (long long)lane * 8;
                float hcc[8], hdd[8];
                if (hb + 8 <= (long long)n) {
                    float rr[8], vv[8], nn[8];
                    *(float4*)(rr)     = __ldg((const float4*)(rewards + hb));
                    *(float4*)(rr + 4) = __ldg((const float4*)(rewards + hb) + 1);
                    *(float4*)(vv)     = __ldg((const float4*)(values + hb));
                    *(float4*)(vv + 4) = __ldg((const float4*)(values + hb) + 1);
                    *(float4*)(nn)     = __ldg((const float4*)(next_values + hb));
                    *(float4*)(nn + 4) = __ldg((const float4*)(next_values + hb) + 1);
                    int te[8], tu[8];
                    if (byteLayout) {
                        unsigned long long tm = *(const unsigned long long*)((const uint8_t*)term_raw + hb);
                        unsigned long long tr = *(const unsigned long long*)((const uint8_t*)trun_raw + hb);
#pragma unroll
                        for (int j = 0; j < 8; j++) {
                            te[j] = (int)((tm >> (8 * j)) & 0xFFull);
                            tu[j] = (int)((tr >> (8 * j)) & 0xFFull);
                        }
                    } else {
                        const int4* tm4 = (const int4*)((const int*)term_raw + hb);
                        const int4* tr4 = (const int4*)((const int*)trun_raw + hb);
                        int4 a0 = __ldg(tm4), a1 = __ldg(tm4 + 1);
                        int4 b0 = __ldg(tr4), b1 = __ldg(tr4 + 1);
                        te[0]=a0.x; te[1]=a0.y; te[2]=a0.z; te[3]=a0.w;
                        te[4]=a1.x; te[5]=a1.y; te[6]=a1.z; te[7]=a1.w;
                        tu[0]=b0.x; tu[1]=b0.y; tu[2]=b0.z; tu[3]=b0.w;
                        tu[4]=b1.x; tu[5]=b1.y; tu[6]=b1.z; tu[7]=b1.w;
                    }
#pragma unroll
                    for (int j = 0; j < 8; j++) {
                        bool b_te = te[j] != 0, b_tu = tu[j] != 0;
                        float nt = b_te ? 0.f : 1.f;
                        hdd[j] = rr[j] + GAMMA_F * nt * nn[j] - vv[j];
                        hcc[j] = (b_te || b_tu) ? 0.f : GL;
                    }
                } else {
#pragma unroll
                    for (int j = 0; j < 8; j++) {
                        long long idx = hb + j;
                        if (idx < (long long)n) {
                            bool b_te, b_tu;
                            if (byteLayout) {
                                b_te = ((const uint8_t*)term_raw)[idx] != 0;
                                b_tu = ((const uint8_t*)trun_raw)[idx] != 0;
                            } else {
                                b_te = ((const int*)term_raw)[idx] != 0;
                                b_tu = ((const int*)trun_raw)[idx] != 0;
                            }
                            float nt = b_te ? 0.f : 1.f;
                            hdd[j] = rewards[idx] + GAMMA_F * nt * next_values[idx] - values[idx];
                            hcc[j] = (b_te || b_tu) ? 0.f : GL;
                        } else { hcc[j] = 1.f; hdd[j] = 0.f; }
                    }
                }
#pragma unroll
                for (int j = 7; j >= 0; j--) { hD = fmaf(hcc[j], hD, hdd[j]); hC *= hcc[j]; }
                // warp suffix scan
#pragma unroll
                for (int off = 1; off < 32; off <<= 1) {
                    float oc = __shfl_down_sync(0xFFFFFFFFu, hC, off);
                    float od = __shfl_down_sync(0xFFFFFFFFu, hD, off);
                    float nD = fmaf(hC, od, hD);
                    float nC = hC * oc;
                    if (lane + off < 32) { hC = nC; hD = nD; }
                }
            } else { hD = 0.f; }
            if (lane == 0) s_seed[0] = hD;   // seed applied to x=0 beyond halo
        }

        // --- chunk loop: right to left, carry via s_seed parity ---
        int iter = 0;
        for (int c = cEnd - 1; c >= cBeg; c--, iter++) {
            const long long base = (long long)c * CHUNK + t * SEG;
            float cc[SEG], dd[SEG];
            const bool full = (base + SEG <= (long long)n);
            if (full) {
                float4 rr = __ldg((const float4*)(rewards + base));
                float4 vv = __ldg((const float4*)(values + base));
                float4 nn = __ldg((const float4*)(next_values + base));
                int te[4], tu[4];
                if (byteLayout) {
                    unsigned tm = *(const unsigned*)((const uint8_t*)term_raw + base);
                    unsigned tr = *(const unsigned*)((const uint8_t*)trun_raw + base);
#pragma unroll
                    for (int j = 0; j < 4; j++) {
                        te[j] = (int)((tm >> (8 * j)) & 0xFFu);
                        tu[j] = (int)((tr >> (8 * j)) & 0xFFu);
                    }
                } else {
                    int4 a0 = __ldg((const int4*)((const int*)term_raw + base));
                    int4 b0 = __ldg((const int4*)((const int*)trun_raw + base));
                    te[0]=a0.x; te[1]=a0.y; te[2]=a0.z; te[3]=a0.w;
                    tu[0]=b0.x; tu[1]=b0.y; tu[2]=b0.z; tu[3]=b0.w;
                }
                float r4[4] = {rr.x, rr.y, rr.z, rr.w};
                float v4[4] = {vv.x, vv.y, vv.z, vv.w};
                float n4[4] = {nn.x, nn.y, nn.z, nn.w};
#pragma unroll
                for (int j = 0; j < 4; j++) {
                    bool b_te = te[j] != 0, b_tu = tu[j] != 0;
                    float nt = b_te ? 0.f : 1.f;
                    dd[j] = r4[j] + GAMMA_F * nt * n4[j] - v4[j];
                    cc[j] = (b_te || b_tu) ? 0.f : GL;
                }
            } else {
#pragma unroll
                for (int j = 0; j < 4; j++) {
                    long long idx = base + j;
                    if (idx < (long long)n) {
                        bool b_te, b_tu;
                        if (byteLayout) {
                            b_te = ((const uint8_t*)term_raw)[idx] != 0;
                            b_tu = ((const uint8_t*)trun_raw)[idx] != 0;
                        } else {
                            b_te = ((const int*)term_raw)[idx] != 0;
                            b_tu = ((const int*)trun_raw)[idx] != 0;
                        }
                        float nt = b_te ? 0.f : 1.f;
                        dd[j] = rewards[idx] + GAMMA_F * nt * next_values[idx] - values[idx];
                        cc[j] = (b_te || b_tu) ? 0.f : GL;
                    } else { cc[j] = 1.f; dd[j] = 0.f; }
                }
            }

            float C = 1.f, D = 0.f;
#pragma unroll
            for (int j = SEG - 1; j >= 0; j--) { D = fmaf(cc[j], D, dd[j]); C *= cc[j]; }

            float iC = C, iD = D;
#pragma unroll
            for (int off = 1; off < 32; off <<= 1) {
                float oc = __shfl_down_sync(0xFFFFFFFFu, iC, off);
                float od = __shfl_down_sync(0xFFFFFFFFu, iD, off);
                float nD = fmaf(iC, od, iD);
                float nC = iC * oc;
                if (lane + off < 32) { iC = nC; iD = nD; }
            }
            float eC = __shfl_down_sync(0xFFFFFFFFu, iC, 1);
            float eD = __shfl_down_sync(0xFFFFFFFFu, iD, 1);
            if (lane == 31) { eC = 1.f; eD = 0.f; }

            if (lane == 0) { s_aggC[wrp] = iC; s_aggD[wrp] = iD; }
            __syncthreads();

            const float seed = s_seed[iter & 1];
            float win = seed;
            for (int j = (BLOCK / 32) - 1; j > wrp; j--)
                win = fmaf(s_aggC[j], win, s_aggD[j]);
            if (t == 0)
                s_seed[(iter + 1) & 1] = fmaf(s_aggC[0], win, s_aggD[0]);  // carry = adv at chunk start

            float x = fmaf(eC, win, eD);
            if (full) {
                float o0, o1, o2, o3;
                x = fmaf(cc[3], x, dd[3]); o3 = x; accSum += x; accSq = fmaf(x, x, accSq);
                x = fmaf(cc[2], x, dd[2]); o2 = x; accSum += x; accSq = fmaf(x, x, accSq);
                x = fmaf(cc[1], x, dd[1]); o1 = x; accSum += x; accSq = fmaf(x, x, accSq);
                x = fmaf(cc[0], x, dd[0]); o0 = x; accSum += x; accSq = fmaf(x, x, accSq);
                *(float4*)(g_adv + base) = make_float4(o0, o1, o2, o3);
            } else {
#pragma unroll
                for (int j = SEG - 1; j >= 0; j--) {
                    x = fmaf(cc[j], x, dd[j]);
                    long long idx = base + j;
                    if (idx < (long long)n) {
                        g_adv[idx] = x;
                        accSum += x; accSq = fmaf(x, x, accSq);
                    }
                }
            }
            __syncthreads();   // protect s_agg/s_seed reuse
        }
    }

    // ---- per-block partials (no global atomics on data path) ----
    {
        double ds = (double)accSum, dq = (double)accSq;
#pragma unroll
        for (int o = 16; o > 0; o >>= 1) {
            ds += __shfl_down_sync(0xFFFFFFFFu, ds, o);
            dq += __shfl_down_sync(0xFFFFFFFFu, dq, o);
        }
        if (lane == 0) { s_wsum[wrp] = ds; s_wsq[wrp] = dq; }
        __syncthreads();
        if (t == 0) {
            double ts = 0.0, tq = 0.0;
#pragma unroll
            for (int w = 0; w < BLOCK / 32; w++) { ts += s_wsum[w]; tq += s_wsq[w]; }
            g_psum[blockIdx.x] = ts;
            g_psq[blockIdx.x]  = tq;
        }
    }

    // ===== grid barrier (correct fencing: every thread fences, then sync, then arrive) =====
    __threadfence();
    __syncthreads();
    if (t == 0) {
        atomicAdd(&g_done, 1);
        volatile int* vd = &g_done;
        while (*vd < GRID) __nanosleep(128);
    }
    __syncthreads();
    __threadfence();

    // ---- every block reduces the partial arrays (L2-resident, redundant but cheap) ----
    {
        double ds = 0.0, dq = 0.0;
        for (int i = t; i < GRID; i += BLOCK) { ds += g_psum[i]; dq += g_psq[i]; }
#pragma unroll
        for (int o = 16; o > 0; o >>= 1) {
            ds += __shfl_down_sync(0xFFFFFFFFu, ds, o);
            dq += __shfl_down_sync(0xFFFFFFFFu, dq, o);
        }
        if (lane == 0) { s_wsum[wrp] = ds; s_wsq[wrp] = dq; }
        __syncthreads();
        if (t == 0) {
            double ts = 0.0, tq = 0.0;
#pragma unroll
            for (int w = 0; w < BLOCK / 32; w++) { ts += s_wsum[w]; tq += s_wsq[w]; }
            double mean = ts / (double)n;
            double var = (tq - ts * ts / (double)n) / (double)(n - 1);
            if (var < 0.0) var = 0.0;
            s_mean = (float)mean;
            s_rinv = (float)(1.0 / (sqrt(var) + 1e-9));
        }
        __syncthreads();
    }
    const float mean = s_mean, rinv = s_rinv;

    // ===== phase 2: epilogue =====
    const long long nv4 = n / 4;
    const long long stride = (long long)GRID * BLOCK;
    for (long long i4 = (long long)blockIdx.x * BLOCK + t; i4 < nv4; i4 += stride) {
        long long b4 = i4 * 4;
        float4 a   = *(const float4*)(g_adv + b4);
        float4 v   = __ldg((const float4*)(values + b4));
        float4 lp  = __ldcs((const float4*)(log_probs + b4));
        float4 olp = __ldcs((const float4*)(old_log_probs + b4));
        float o[12];
        ppo_row(a.x, v.x, lp.x, olp.x, mean, rinv, o + 0);
        ppo_row(a.y, v.y, lp.y, olp.y, mean, rinv, o + 3);
        ppo_row(a.z, v.z, lp.z, olp.z, mean, rinv, o + 6);
        ppo_row(a.w, v.w, lp.w, olp.w, mean, rinv, o + 9);
        float4* dst = (float4*)(out + b4 * 3);
        __stcs(dst + 0, make_float4(o[0], o[1], o[2],  o[3]));
        __stcs(dst + 1, make_float4(o[4], o[5], o[6],  o[7]));
        __stcs(dst + 2, make_float4(o[8], o[9], o[10], o[11]));
    }
    if (blockIdx.x == 0 && t == 0) {
        for (long long i = nv4 * 4; i < (long long)n; i++) {
            float o[3];
            ppo_row(g_adv[i], values[i], log_probs[i], old_log_probs[i], mean, rinv, o);
            out[i * 3 + 0] = o[0];
            out[i * 3 + 1] = o[1];
            out[i * 3 + 2] = o[2];
        }
    }

    // ---- self-reset of barrier state (last block to arrive here resets both) ----
    if (t == 0) {
        int tk = atomicAdd(&g_done2, 1);
        if (tk == GRID - 1) { g_done = 0; g_done2 = 0; }
    }
}

extern "C" void kernel_launch(void* const* d_in, const int* in_sizes, int n_in,
                              void* d_out, int out_size) {
    const float* rewards       = (const float*)d_in[0];
    const float* values        = (const float*)d_in[1];
    const float* next_values   = (const float*)d_in[2];
    const float* log_probs     = (const float*)d_in[3];
    const float* old_log_probs = (const float*)d_in[4];
    const void*  terminated    = d_in[5];
    const void*  truncated     = d_in[6];
    float* out = (float*)d_out;

    int n = in_sizes[0];
    int numChunks  = (n + CHUNK - 1) / CHUNK;          // 2048 for N=2M
    int numRegions = (numChunks + CPR - 1) / CPR;      // 683

    fused_kernel<<<GRID, BLOCK>>>(rewards, values, next_values,
                                  log_probs, old_log_probs,
                                  terminated, truncated, out,
                                  n, numChunks, numRegions);
}

// round 7
// speedup vs baseline: 1.2960x; 1.1475x over previous
#include <cuda_runtime.h>
#include <stdint.h>

#define BLOCK 256
#define WARPS 8                    // warps per block
#define SEG 16                     // elements per thread in scan
#define TILE (32 * SEG)            // 512 elements per warp tile
#define HALO 128                   // halo elements (4 per lane)
#define MAXBLK 8192

#define GAMMA_F 0.99f
#define LAMBDA_F 0.95f
#define CLIP_EPS_F 0.2f

// ---- device scratch ----
__device__ float  g_adv[1 << 22];
__device__ double g_psum[MAXBLK];
__device__ double g_psq[MAXBLK];
__device__ float  g_mean;
__device__ float  g_rinv;

// load 4 (c,d) pairs for elements [b, b+4) with bounds guard
__device__ __forceinline__ void load_cd4(long long b, int n, int byteLayout,
                                         const float* __restrict__ rewards,
                                         const float* __restrict__ values,
                                         const float* __restrict__ next_values,
                                         const void* __restrict__ term_raw,
                                         const void* __restrict__ trun_raw,
                                         float* cc, float* dd) {
    const float GL = GAMMA_F * LAMBDA_F;
    if (b + 4 <= (long long)n && (b & 3) == 0) {
        float4 rr = __ldg((const float4*)(rewards + b));
        float4 vv = __ldg((const float4*)(values + b));
        float4 nn = __ldg((const float4*)(next_values + b));
        int te[4], tu[4];
        if (byteLayout) {
            unsigned tm = *(const unsigned*)((const uint8_t*)term_raw + b);
            unsigned tr = *(const unsigned*)((const uint8_t*)trun_raw + b);
#pragma unroll
            for (int j = 0; j < 4; j++) {
                te[j] = (int)((tm >> (8 * j)) & 0xFFu);
                tu[j] = (int)((tr >> (8 * j)) & 0xFFu);
            }
        } else {
            int4 a0 = __ldg((const int4*)((const int*)term_raw + b));
            int4 b0 = __ldg((const int4*)((const int*)trun_raw + b));
            te[0]=a0.x; te[1]=a0.y; te[2]=a0.z; te[3]=a0.w;
            tu[0]=b0.x; tu[1]=b0.y; tu[2]=b0.z; tu[3]=b0.w;
        }
        float r4[4] = {rr.x, rr.y, rr.z, rr.w};
        float v4[4] = {vv.x, vv.y, vv.z, vv.w};
        float n4[4] = {nn.x, nn.y, nn.z, nn.w};
#pragma unroll
        for (int j = 0; j < 4; j++) {
            bool b_te = te[j] != 0, b_tu = tu[j] != 0;
            float nt = b_te ? 0.f : 1.f;
            dd[j] = r4[j] + GAMMA_F * nt * n4[j] - v4[j];
            cc[j] = (b_te || b_tu) ? 0.f : GL;
        }
    } else {
#pragma unroll
        for (int j = 0; j < 4; j++) {
            long long idx = b + j;
            if (idx < (long long)n) {
                bool b_te, b_tu;
                if (byteLayout) {
                    b_te = ((const uint8_t*)term_raw)[idx] != 0;
                    b_tu = ((const uint8_t*)trun_raw)[idx] != 0;
                } else {
                    b_te = ((const int*)term_raw)[idx] != 0;
                    b_tu = ((const int*)trun_raw)[idx] != 0;
                }
                float nt = b_te ? 0.f : 1.f;
                dd[j] = rewards[idx] + GAMMA_F * nt * next_values[idx] - values[idx];
                cc[j] = (b_te || b_tu) ? 0.f : GL;
            } else { cc[j] = 1.f; dd[j] = 0.f; }
        }
    }
}

// ===== kernel A: warp-autonomous scan, one 512-elem tile per warp =====
__global__ __launch_bounds__(BLOCK)
void scan_kernel(const float* __restrict__ rewards,
                 const float* __restrict__ values,
                 const float* __restrict__ next_values,
                 const void* __restrict__ term_raw,
                 const void* __restrict__ trun_raw,
                 int n, int numTiles)
{
    __shared__ double s_wsum[WARPS];
    __shared__ double s_wsq[WARPS];

    const int t = threadIdx.x;
    const int lane = t & 31;
    const int wrp  = t >> 5;

    // per-block bool-layout detection (first 1KB, L2-broadcast)
    int pred = 0;
    if (t < 64 && n >= 1024) {
        uint4 x = __ldg((const uint4*)term_raw + t);
        uint4 y = __ldg((const uint4*)trun_raw + t);
        pred = ((x.x | x.y | x.z | x.w | y.x | y.y | y.z | y.w) & 0xFFFFFF00u) != 0;
    }
    const int byteLayout = __syncthreads_or(pred);

    float accSum = 0.f, accSq = 0.f;
    const int tile = blockIdx.x * WARPS + wrp;

    if (tile < numTiles) {
        const long long tileStart = (long long)tile * TILE;
        const long long tileEnd   = tileStart + TILE;

        // ---- main tile loads: 16 elems per thread (issued before halo math) ----
        float cc[SEG], dd[SEG];
        const long long base = tileStart + (long long)lane * SEG;
#pragma unroll
        for (int g = 0; g < SEG / 4; g++)
            load_cd4(base + g * 4, n, byteLayout,
                     rewards, values, next_values, term_raw, trun_raw,
                     cc + g * 4, dd + g * 4);

        // ---- halo: 4 elems per lane => 128-element seed composition ----
        float hC = 1.f, hD = 0.f;
        if (tileEnd < (long long)n) {
            float hcc[4], hdd[4];
            load_cd4(tileEnd + (long long)lane * 4, n, byteLayout,
                     rewards, values, next_values, term_raw, trun_raw, hcc, hdd);
#pragma unroll
            for (int j = 3; j >= 0; j--) { hD = fmaf(hcc[j], hD, hdd[j]); hC *= hcc[j]; }
#pragma unroll
            for (int off = 1; off < 32; off <<= 1) {
                float oc = __shfl_down_sync(0xFFFFFFFFu, hC, off);
                float od = __shfl_down_sync(0xFFFFFFFFu, hD, off);
                float nD = fmaf(hC, od, hD);
                float nC = hC * oc;
                if (lane + off < 32) { hC = nC; hD = nD; }
            }
        }
        const float seed = __shfl_sync(0xFFFFFFFFu, hD, 0);  // adv value at tileEnd

        // ---- per-thread segment composition over 16 elements ----
        float C = 1.f, D = 0.f;
#pragma unroll
        for (int j = SEG - 1; j >= 0; j--) { D = fmaf(cc[j], D, dd[j]); C *= cc[j]; }

        // warp suffix scan
        float iC = C, iD = D;
#pragma unroll
        for (int off = 1; off < 32; off <<= 1) {
            float oc = __shfl_down_sync(0xFFFFFFFFu, iC, off);
            float od = __shfl_down_sync(0xFFFFFFFFu, iD, off);
            float nD = fmaf(iC, od, iD);
            float nC = iC * oc;
            if (lane + off < 32) { iC = nC; iD = nD; }
        }
        float eC = __shfl_down_sync(0xFFFFFFFFu, iC, 1);
        float eD = __shfl_down_sync(0xFFFFFFFFu, iD, 1);
        if (lane == 31) { eC = 1.f; eD = 0.f; }

        // x = adv value right after this thread's 16-elem segment
        float x = fmaf(eC, seed, eD);
        float outv[SEG];
#pragma unroll
        for (int j = SEG - 1; j >= 0; j--) {
            x = fmaf(cc[j], x, dd[j]);
            outv[j] = x;
        }

        if (base + SEG <= (long long)n) {
#pragma unroll
            for (int j = 0; j < SEG; j++) { accSum += outv[j]; accSq = fmaf(outv[j], outv[j], accSq); }
#pragma unroll
            for (int g = 0; g < SEG / 4; g++)
                *(float4*)(g_adv + base + g * 4) =
                    make_float4(outv[g*4], outv[g*4+1], outv[g*4+2], outv[g*4+3]);
        } else {
#pragma unroll
            for (int j = 0; j < SEG; j++) {
                long long idx = base + j;
                if (idx < (long long)n) {
                    g_adv[idx] = outv[j];
                    accSum += outv[j]; accSq = fmaf(outv[j], outv[j], accSq);
                }
            }
        }
    }

    // ---- block partial sums ----
    double ds = (double)accSum, dq = (double)accSq;
#pragma unroll
    for (int o = 16; o > 0; o >>= 1) {
        ds += __shfl_down_sync(0xFFFFFFFFu, ds, o);
        dq += __shfl_down_sync(0xFFFFFFFFu, dq, o);
    }
    if (lane == 0) { s_wsum[wrp] = ds; s_wsq[wrp] = dq; }
    __syncthreads();
    if (t == 0) {
        double ts = 0.0, tq = 0.0;
#pragma unroll
        for (int w = 0; w < WARPS; w++) { ts += s_wsum[w]; tq += s_wsq[w]; }
        g_psum[blockIdx.x] = ts;
        g_psq[blockIdx.x]  = tq;
    }
}

// ===== kernel B: reduce partials -> mean, 1/(std+eps) =====
__global__ void stats_kernel(int numBlocks, int n) {
    __shared__ double s_wsum[8];
    __shared__ double s_wsq[8];
    const int t = threadIdx.x;
    const int lane = t & 31, wrp = t >> 5;
    double ds = 0.0, dq = 0.0;
    for (int i = t; i < numBlocks; i += 256) { ds += g_psum[i]; dq += g_psq[i]; }
#pragma unroll
    for (int o = 16; o > 0; o >>= 1) {
        ds += __shfl_down_sync(0xFFFFFFFFu, ds, o);
        dq += __shfl_down_sync(0xFFFFFFFFu, dq, o);
    }
    if (lane == 0) { s_wsum[wrp] = ds; s_wsq[wrp] = dq; }
    __syncthreads();
    if (t == 0) {
        double ts = 0.0, tq = 0.0;
#pragma unroll
        for (int w = 0; w < 8; w++) { ts += s_wsum[w]; tq += s_wsq[w]; }
        double mean = ts / (double)n;
        double var = (tq - ts * ts / (double)n) / (double)(n - 1);
        if (var < 0.0) var = 0.0;
        g_mean = (float)mean;
        g_rinv = (float)(1.0 / (sqrt(var) + 1e-9));
    }
}

__device__ __forceinline__ void ppo_row(float a, float v, float lp, float olp,
                                        float mean, float rinv, float* o) {
    float an = (a - mean) * rinv;
    float lr = a + v;
    float ratio = __expf(lp - olp);
    float cl = fminf(fmaxf(ratio, 1.f - CLIP_EPS_F), 1.f + CLIP_EPS_F);
    float loss = -fminf(ratio * an, cl * an);
    o[0] = an; o[1] = lr; o[2] = loss;
}

// ===== kernel C: streaming epilogue, one float4 per thread =====
__global__ __launch_bounds__(BLOCK)
void output_kernel(const float* __restrict__ values,
                   const float* __restrict__ log_probs,
                   const float* __restrict__ old_log_probs,
                   float* __restrict__ out, int n)
{
    const float mean = g_mean, rinv = g_rinv;
    const long long i4 = (long long)blockIdx.x * BLOCK + threadIdx.x;
    const long long b4 = i4 * 4;
    if (b4 + 4 <= (long long)n) {
        float4 a   = *(const float4*)(g_adv + b4);
        float4 v   = __ldg((const float4*)(values + b4));
        float4 lp  = __ldg((const float4*)(log_probs + b4));
        float4 olp = __ldg((const float4*)(old_log_probs + b4));
        float o[12];
        ppo_row(a.x, v.x, lp.x, olp.x, mean, rinv, o + 0);
        ppo_row(a.y, v.y, lp.y, olp.y, mean, rinv, o + 3);
        ppo_row(a.z, v.z, lp.z, olp.z, mean, rinv, o + 6);
        ppo_row(a.w, v.w, lp.w, olp.w, mean, rinv, o + 9);
        float4* dst = (float4*)(out + b4 * 3);
        __stcs(dst + 0, make_float4(o[0], o[1], o[2],  o[3]));
        __stcs(dst + 1, make_float4(o[4], o[5], o[6],  o[7]));
        __stcs(dst + 2, make_float4(o[8], o[9], o[10], o[11]));
    } else if (b4 < (long long)n) {
        for (long long i = b4; i < (long long)n; i++) {
            float o[3];
            ppo_row(g_adv[i], values[i], log_probs[i], old_log_probs[i], mean, rinv, o);
            out[i * 3 + 0] = o[0];
            out[i * 3 + 1] = o[1];
            out[i * 3 + 2] = o[2];
        }
    }
}

extern "C" void kernel_launch(void* const* d_in, const int* in_sizes, int n_in,
                              void* d_out, int out_size) {
    const float* rewards       = (const float*)d_in[0];
    const float* values        = (const float*)d_in[1];
    const float* next_values   = (const float*)d_in[2];
    const float* log_probs     = (const float*)d_in[3];
    const float* old_log_probs = (const float*)d_in[4];
    const void*  terminated    = d_in[5];
    const void*  truncated     = d_in[6];
    float* out = (float*)d_out;

    int n = in_sizes[0];
    int numTiles = (n + TILE - 1) / TILE;              // 4096 for N=2M
    int gridA = (numTiles + WARPS - 1) / WARPS;        // 512
    if (gridA > MAXBLK) gridA = MAXBLK;                // (N<=4M by scratch size)
    long long nv4 = ((long long)n + 3) / 4;
    int gridC = (int)((nv4 + BLOCK - 1) / BLOCK);      // 2048

    scan_kernel<<<gridA, BLOCK>>>(rewards, values, next_values,
                                  terminated, truncated, n, numTiles);
    stats_kernel<<<1, 256>>>(gridA, n);
    output_kernel<<<gridC, BLOCK>>>(values, log_probs, old_log_probs, out, n);
}

// round 8
// speedup vs baseline: 1.4611x; 1.1274x over previous
#include <cuda_runtime.h>
#include <stdint.h>

#define BLOCK 256
#define WARPS 8
#define TILE 512                   // elements per warp
#define PASS 128                   // elements per pass (4 per lane)
#define NPASS 4
#define MAXBLK 8192

#define GAMMA_F 0.99f
#define LAMBDA_F 0.95f
#define CLIP_EPS_F 0.2f

// ---- device scratch ----
__device__ float  g_adv[1 << 22];
__device__ double g_psum[MAXBLK];
__device__ double g_psq[MAXBLK];
__device__ float  g_mean;
__device__ float  g_rinv;

// guarded load of 4 (c,d) pairs (used for halo / tail only)
__device__ __forceinline__ void load_cd4_guard(long long b, int n, int byteLayout,
                                               const float* __restrict__ rewards,
                                               const float* __restrict__ values,
                                               const float* __restrict__ next_values,
                                               const void* __restrict__ term_raw,
                                               const void* __restrict__ trun_raw,
                                               float* cc, float* dd) {
    const float GL = GAMMA_F * LAMBDA_F;
    if (b + 4 <= (long long)n && (b & 3) == 0) {
        float4 rr = __ldg((const float4*)(rewards + b));
        float4 vv = __ldg((const float4*)(values + b));
        float4 nn = __ldg((const float4*)(next_values + b));
        int te[4], tu[4];
        if (byteLayout) {
            unsigned tm = *(const unsigned*)((const uint8_t*)term_raw + b);
            unsigned tr = *(const unsigned*)((const uint8_t*)trun_raw + b);
#pragma unroll
            for (int j = 0; j < 4; j++) {
                te[j] = (int)((tm >> (8 * j)) & 0xFFu);
                tu[j] = (int)((tr >> (8 * j)) & 0xFFu);
            }
        } else {
            int4 a0 = __ldg((const int4*)((const int*)term_raw + b));
            int4 b0 = __ldg((const int4*)((const int*)trun_raw + b));
            te[0]=a0.x; te[1]=a0.y; te[2]=a0.z; te[3]=a0.w;
            tu[0]=b0.x; tu[1]=b0.y; tu[2]=b0.z; tu[3]=b0.w;
        }
        float r4[4] = {rr.x, rr.y, rr.z, rr.w};
        float v4[4] = {vv.x, vv.y, vv.z, vv.w};
        float n4[4] = {nn.x, nn.y, nn.z, nn.w};
#pragma unroll
        for (int j = 0; j < 4; j++) {
            bool b_te = te[j] != 0, b_tu = tu[j] != 0;
            float nt = b_te ? 0.f : 1.f;
            dd[j] = r4[j] + GAMMA_F * nt * n4[j] - v4[j];
            cc[j] = (b_te || b_tu) ? 0.f : GL;
        }
    } else {
#pragma unroll
        for (int j = 0; j < 4; j++) {
            long long idx = b + j;
            if (idx < (long long)n) {
                bool b_te, b_tu;
                if (byteLayout) {
                    b_te = ((const uint8_t*)term_raw)[idx] != 0;
                    b_tu = ((const uint8_t*)trun_raw)[idx] != 0;
                } else {
                    b_te = ((const int*)term_raw)[idx] != 0;
                    b_tu = ((const int*)trun_raw)[idx] != 0;
                }
                float nt = b_te ? 0.f : 1.f;
                dd[j] = rewards[idx] + GAMMA_F * nt * next_values[idx] - values[idx];
                cc[j] = (b_te || b_tu) ? 0.f : GL;
            } else { cc[j] = 1.f; dd[j] = 0.f; }
        }
    }
}

// warp inclusive suffix scan of affine pairs; returns (iC,iD) per lane
__device__ __forceinline__ void warp_suffix_scan(float& iC, float& iD, int lane) {
#pragma unroll
    for (int off = 1; off < 32; off <<= 1) {
        float oc = __shfl_down_sync(0xFFFFFFFFu, iC, off);
        float od = __shfl_down_sync(0xFFFFFFFFu, iD, off);
        float nD = fmaf(iC, od, iD);
        float nC = iC * oc;
        if (lane + off < 32) { iC = nC; iD = nD; }
    }
}

// ===== kernel A: coalesced warp-autonomous scan =====
__global__ __launch_bounds__(BLOCK)
void scan_kernel(const float* __restrict__ rewards,
                 const float* __restrict__ values,
                 const float* __restrict__ next_values,
                 const void* __restrict__ term_raw,
                 const void* __restrict__ trun_raw,
                 int n, int numTiles)
{
    __shared__ double s_wsum[WARPS];
    __shared__ double s_wsq[WARPS];

    const int t = threadIdx.x;
    const int lane = t & 31;
    const int wrp  = t >> 5;
    const float GL = GAMMA_F * LAMBDA_F;

    int pred = 0;
    if (t < 64 && n >= 1024) {
        uint4 x = __ldg((const uint4*)term_raw + t);
        uint4 y = __ldg((const uint4*)trun_raw + t);
        pred = ((x.x | x.y | x.z | x.w | y.x | y.y | y.z | y.w) & 0xFFFFFF00u) != 0;
    }
    const int byteLayout = __syncthreads_or(pred);

    float accSum = 0.f, accSq = 0.f;
    const int tile = blockIdx.x * WARPS + wrp;

    if (tile < numTiles) {
        const long long tileStart = (long long)tile * TILE;
        const long long tileEnd   = tileStart + TILE;

        if (tileEnd <= (long long)n) {
            // ---------- fast path: fully coalesced ----------
            // prefetch all pass data (independent loads -> deep MLP)
            float4 R[NPASS], V[NPASS], NV[NPASS];
            unsigned TMb[NPASS], TRb[NPASS];
            int4 TMi[NPASS], TRi[NPASS];
#pragma unroll
            for (int p = 0; p < NPASS; p++) {
                const long long b = tileStart + (long long)p * PASS + lane * 4;
                R[p]  = __ldg((const float4*)(rewards + b));
                V[p]  = __ldg((const float4*)(values + b));
                NV[p] = __ldg((const float4*)(next_values + b));
                if (byteLayout) {
                    TMb[p] = *(const unsigned*)((const uint8_t*)term_raw + b);
                    TRb[p] = *(const unsigned*)((const uint8_t*)trun_raw + b);
                } else {
                    TMi[p] = __ldg((const int4*)((const int*)term_raw + b));
                    TRi[p] = __ldg((const int4*)((const int*)trun_raw + b));
                }
            }

            // halo -> seed (adv value at tileEnd)
            float seed = 0.f;
            if (tileEnd < (long long)n) {
                float hcc[4], hdd[4];
                load_cd4_guard(tileEnd + lane * 4, n, byteLayout,
                               rewards, values, next_values, term_raw, trun_raw,
                               hcc, hdd);
                float hC = 1.f, hD = 0.f;
#pragma unroll
                for (int j = 3; j >= 0; j--) { hD = fmaf(hcc[j], hD, hdd[j]); hC *= hcc[j]; }
                warp_suffix_scan(hC, hD, lane);
                seed = __shfl_sync(0xFFFFFFFFu, hD, 0);
            }

            // process passes right-to-left
#pragma unroll
            for (int p = NPASS - 1; p >= 0; p--) {
                float cc[4], dd[4];
                int te[4], tu[4];
                if (byteLayout) {
#pragma unroll
                    for (int j = 0; j < 4; j++) {
                        te[j] = (int)((TMb[p] >> (8 * j)) & 0xFFu);
                        tu[j] = (int)((TRb[p] >> (8 * j)) & 0xFFu);
                    }
                } else {
                    te[0]=TMi[p].x; te[1]=TMi[p].y; te[2]=TMi[p].z; te[3]=TMi[p].w;
                    tu[0]=TRi[p].x; tu[1]=TRi[p].y; tu[2]=TRi[p].z; tu[3]=TRi[p].w;
                }
                float r4[4] = {R[p].x, R[p].y, R[p].z, R[p].w};
                float v4[4] = {V[p].x, V[p].y, V[p].z, V[p].w};
                float n4[4] = {NV[p].x, NV[p].y, NV[p].z, NV[p].w};
#pragma unroll
                for (int j = 0; j < 4; j++) {
                    bool b_te = te[j] != 0, b_tu = tu[j] != 0;
                    float nt = b_te ? 0.f : 1.f;
                    dd[j] = r4[j] + GAMMA_F * nt * n4[j] - v4[j];
                    cc[j] = (b_te || b_tu) ? 0.f : GL;
                }

                float C = 1.f, D = 0.f;
#pragma unroll
                for (int j = 3; j >= 0; j--) { D = fmaf(cc[j], D, dd[j]); C *= cc[j]; }

                float iC = C, iD = D;
                warp_suffix_scan(iC, iD, lane);
                float eC = __shfl_down_sync(0xFFFFFFFFu, iC, 1);
                float eD = __shfl_down_sync(0xFFFFFFFFu, iD, 1);
                if (lane == 31) { eC = 1.f; eD = 0.f; }

                float x = fmaf(eC, seed, eD);
                float o0, o1, o2, o3;
                x = fmaf(cc[3], x, dd[3]); o3 = x;
                x = fmaf(cc[2], x, dd[2]); o2 = x;
                x = fmaf(cc[1], x, dd[1]); o1 = x;
                x = fmaf(cc[0], x, dd[0]); o0 = x;
                accSum += o0 + o1 + o2 + o3;
                accSq = fmaf(o0, o0, accSq); accSq = fmaf(o1, o1, accSq);
                accSq = fmaf(o2, o2, accSq); accSq = fmaf(o3, o3, accSq);

                *(float4*)(g_adv + tileStart + (long long)p * PASS + lane * 4) =
                    make_float4(o0, o1, o2, o3);

                // carry: pass composite (iC,iD at lane 0) applied to seed
                float ns = fmaf(iC, seed, iD);
                seed = __shfl_sync(0xFFFFFFFFu, ns, 0);
            }
        } else {
            // ---------- tail tile (rare): guarded per-pass ----------
            float seed = 0.f;   // halo beyond n
            for (int p = NPASS - 1; p >= 0; p--) {
                float cc[4], dd[4];
                const long long b = tileStart + (long long)p * PASS + lane * 4;
                load_cd4_guard(b, n, byteLayout,
                               rewards, values, next_values, term_raw, trun_raw, cc, dd);
                float C = 1.f, D = 0.f;
#pragma unroll
                for (int j = 3; j >= 0; j--) { D = fmaf(cc[j], D, dd[j]); C *= cc[j]; }
                float iC = C, iD = D;
                warp_suffix_scan(iC, iD, lane);
                float eC = __shfl_down_sync(0xFFFFFFFFu, iC, 1);
                float eD = __shfl_down_sync(0xFFFFFFFFu, iD, 1);
                if (lane == 31) { eC = 1.f; eD = 0.f; }
                float x = fmaf(eC, seed, eD);
#pragma unroll
                for (int j = 3; j >= 0; j--) {
                    x = fmaf(cc[j], x, dd[j]);
                    long long idx = b + j;
                    if (idx < (long long)n) {
                        g_adv[idx] = x;
                        accSum += x; accSq = fmaf(x, x, accSq);
                    }
                }
                float ns = fmaf(iC, seed, iD);
                seed = __shfl_sync(0xFFFFFFFFu, ns, 0);
            }
        }
    }

    // ---- block partial sums ----
    double ds = (double)accSum, dq = (double)accSq;
#pragma unroll
    for (int o = 16; o > 0; o >>= 1) {
        ds += __shfl_down_sync(0xFFFFFFFFu, ds, o);
        dq += __shfl_down_sync(0xFFFFFFFFu, dq, o);
    }
    if (lane == 0) { s_wsum[wrp] = ds; s_wsq[wrp] = dq; }
    __syncthreads();
    if (t == 0) {
        double ts = 0.0, tq = 0.0;
#pragma unroll
        for (int w = 0; w < WARPS; w++) { ts += s_wsum[w]; tq += s_wsq[w]; }
        g_psum[blockIdx.x] = ts;
        g_psq[blockIdx.x]  = tq;
    }
}

// ===== kernel B: reduce partials =====
__global__ void stats_kernel(int numBlocks, int n) {
    __shared__ double s_wsum[8];
    __shared__ double s_wsq[8];
    const int t = threadIdx.x;
    const int lane = t & 31, wrp = t >> 5;
    double ds = 0.0, dq = 0.0;
    for (int i = t; i < numBlocks; i += 256) { ds += g_psum[i]; dq += g_psq[i]; }
#pragma unroll
    for (int o = 16; o > 0; o >>= 1) {
        ds += __shfl_down_sync(0xFFFFFFFFu, ds, o);
        dq += __shfl_down_sync(0xFFFFFFFFu, dq, o);
    }
    if (lane == 0) { s_wsum[wrp] = ds; s_wsq[wrp] = dq; }
    __syncthreads();
    if (t == 0) {
        double ts = 0.0, tq = 0.0;
#pragma unroll
        for (int w = 0; w < 8; w++) { ts += s_wsum[w]; tq += s_wsq[w]; }
        double mean = ts / (double)n;
        double var = (tq - ts * ts / (double)n) / (double)(n - 1);
        if (var < 0.0) var = 0.0;
        g_mean = (float)mean;
        g_rinv = (float)(1.0 / (sqrt(var) + 1e-9));
    }
}

__device__ __forceinline__ void ppo_row(float a, float v, float lp, float olp,
                                        float mean, float rinv, float* o) {
    float an = (a - mean) * rinv;
    float lr = a + v;
    float ratio = __expf(lp - olp);
    float cl = fminf(fmaxf(ratio, 1.f - CLIP_EPS_F), 1.f + CLIP_EPS_F);
    float loss = -fminf(ratio * an, cl * an);
    o[0] = an; o[1] = lr; o[2] = loss;
}

// ===== kernel C: epilogue with smem-staged coalesced output =====
__global__ __launch_bounds__(BLOCK)
void output_kernel(const float* __restrict__ values,
                   const float* __restrict__ log_probs,
                   const float* __restrict__ old_log_probs,
                   float* __restrict__ out, int n)
{
    __shared__ float4 s4[3 * BLOCK];
    const float mean = g_mean, rinv = g_rinv;
    const int t = threadIdx.x;
    const long long blockBase = (long long)blockIdx.x * (BLOCK * 4);   // elements
    const long long b4 = blockBase + t * 4;

    if (blockBase + BLOCK * 4 <= (long long)n) {
        float4 a   = *(const float4*)(g_adv + b4);
        float4 v   = __ldg((const float4*)(values + b4));
        float4 lp  = __ldg((const float4*)(log_probs + b4));
        float4 olp = __ldg((const float4*)(old_log_probs + b4));
        float o[12];
        ppo_row(a.x, v.x, lp.x, olp.x, mean, rinv, o + 0);
        ppo_row(a.y, v.y, lp.y, olp.y, mean, rinv, o + 3);
        ppo_row(a.z, v.z, lp.z, olp.z, mean, rinv, o + 6);
        ppo_row(a.w, v.w, lp.w, olp.w, mean, rinv, o + 9);
        // stage: s4[i] holds out-floats [4i, 4i+4) of this block's 3072-float region
        s4[3 * t + 0] = make_float4(o[0], o[1], o[2],  o[3]);
        s4[3 * t + 1] = make_float4(o[4], o[5], o[6],  o[7]);
        s4[3 * t + 2] = make_float4(o[8], o[9], o[10], o[11]);
        __syncthreads();
        float4* dst = (float4*)(out + blockBase * 3);
        __stcs(dst + t,             s4[t]);
        __stcs(dst + t + BLOCK,     s4[t + BLOCK]);
        __stcs(dst + t + 2 * BLOCK, s4[t + 2 * BLOCK]);
    } else {
        for (long long i = b4; i < b4 + 4 && i < (long long)n; i++) {
            float o[3];
            ppo_row(g_adv[i], values[i], log_probs[i], old_log_probs[i], mean, rinv, o);
            out[i * 3 + 0] = o[0];
            out[i * 3 + 1] = o[1];
            out[i * 3 + 2] = o[2];
        }
    }
}

extern "C" void kernel_launch(void* const* d_in, const int* in_sizes, int n_in,
                              void* d_out, int out_size) {
    const float* rewards       = (const float*)d_in[0];
    const float* values        = (const float*)d_in[1];
    const float* next_values   = (const float*)d_in[2];
    const float* log_probs     = (const float*)d_in[3];
    const float* old_log_probs = (const float*)d_in[4];
    const void*  terminated    = d_in[5];
    const void*  truncated     = d_in[6];
    float* out = (float*)d_out;

    int n = in_sizes[0];
    int numTiles = (n + TILE - 1) / TILE;              // 4096 for N=2M
    int gridA = (numTiles + WARPS - 1) / WARPS;        // 512
    if (gridA > MAXBLK) gridA = MAXBLK;
    int gridC = (int)(((long long)n + BLOCK * 4 - 1) / (BLOCK * 4));   // 2048

    scan_kernel<<<gridA, BLOCK>>>(rewards, values, next_values,
                                  terminated, truncated, n, numTiles);
    stats_kernel<<<1, 256>>>(gridA, n);
    output_kernel<<<gridC, BLOCK>>>(values, log_probs, old_log_probs, out, n);
}

// round 9
// speedup vs baseline: 1.5804x; 1.0816x over previous
#include <cuda_runtime.h>
#include <stdint.h>

#define BLOCK 256
#define WARPS 8
#define TILE 512                   // elements per warp
#define PASS 128                   // elements per pass (4 per lane)
#define NPASS 4
#define MAXBLK 8192

#define GAMMA_F 0.99f
#define LAMBDA_F 0.95f
#define CLIP_EPS_F 0.2f
#define GL (GAMMA_F * LAMBDA_F)
#define GL4 (GL * GL * GL * GL)

// ---- device scratch ----
__device__ float  g_adv[1 << 22];
__device__ double g_psum[MAXBLK];
__device__ double g_psq[MAXBLK];
__device__ float  g_mean;
__device__ float  g_rinv;

// guarded load of 4 (c,d) pairs (halo / tail only)
__device__ __forceinline__ void load_cd4_guard(long long b, int n, int byteLayout,
                                               const float* __restrict__ rewards,
                                               const float* __restrict__ values,
                                               const float* __restrict__ next_values,
                                               const void* __restrict__ term_raw,
                                               const void* __restrict__ trun_raw,
                                               float* cc, float* dd) {
    if (b + 4 <= (long long)n && (b & 3) == 0) {
        float4 rr = __ldg((const float4*)(rewards + b));
        float4 vv = __ldg((const float4*)(values + b));
        float4 nn = __ldg((const float4*)(next_values + b));
        int te[4], tu[4];
        if (byteLayout) {
            unsigned tm = *(const unsigned*)((const uint8_t*)term_raw + b);
            unsigned tr = *(const unsigned*)((const uint8_t*)trun_raw + b);
#pragma unroll
            for (int j = 0; j < 4; j++) {
                te[j] = (int)((tm >> (8 * j)) & 0xFFu);
                tu[j] = (int)((tr >> (8 * j)) & 0xFFu);
            }
        } else {
            int4 a0 = __ldg((const int4*)((const int*)term_raw + b));
            int4 b0 = __ldg((const int4*)((const int*)trun_raw + b));
            te[0]=a0.x; te[1]=a0.y; te[2]=a0.z; te[3]=a0.w;
            tu[0]=b0.x; tu[1]=b0.y; tu[2]=b0.z; tu[3]=b0.w;
        }
        float r4[4] = {rr.x, rr.y, rr.z, rr.w};
        float v4[4] = {vv.x, vv.y, vv.z, vv.w};
        float n4[4] = {nn.x, nn.y, nn.z, nn.w};
#pragma unroll
        for (int j = 0; j < 4; j++) {
            bool b_te = te[j] != 0, b_tu = tu[j] != 0;
            float nt = b_te ? 0.f : 1.f;
            dd[j] = r4[j] + GAMMA_F * nt * n4[j] - v4[j];
            cc[j] = (b_te || b_tu) ? 0.f : GL;
        }
    } else {
#pragma unroll
        for (int j = 0; j < 4; j++) {
            long long idx = b + j;
            if (idx < (long long)n) {
                bool b_te, b_tu;
                if (byteLayout) {
                    b_te = ((const uint8_t*)term_raw)[idx] != 0;
                    b_tu = ((const uint8_t*)trun_raw)[idx] != 0;
                } else {
                    b_te = ((const int*)term_raw)[idx] != 0;
                    b_tu = ((const int*)trun_raw)[idx] != 0;
                }
                float nt = b_te ? 0.f : 1.f;
                dd[j] = rewards[idx] + GAMMA_F * nt * next_values[idx] - values[idx];
                cc[j] = (b_te || b_tu) ? 0.f : GL;
            } else { cc[j] = 1.f; dd[j] = 0.f; }
        }
    }
}

__device__ __forceinline__ void warp_suffix_scan(float& iC, float& iD, int lane) {
#pragma unroll
    for (int off = 1; off < 32; off <<= 1) {
        float oc = __shfl_down_sync(0xFFFFFFFFu, iC, off);
        float od = __shfl_down_sync(0xFFFFFFFFu, iD, off);
        float nD = fmaf(iC, od, iD);
        float nC = iC * oc;
        if (lane + off < 32) { iC = nC; iD = nD; }
    }
}

// ===== kernel A: coalesced scan, compact register state =====
__global__ __launch_bounds__(BLOCK, 4)
void scan_kernel(const float* __restrict__ rewards,
                 const float* __restrict__ values,
                 const float* __restrict__ next_values,
                 const void* __restrict__ term_raw,
                 const void* __restrict__ trun_raw,
                 int n, int numTiles)
{
    __shared__ double s_wsum[WARPS];
    __shared__ double s_wsq[WARPS];

    const int t = threadIdx.x;
    const int lane = t & 31;
    const int wrp  = t >> 5;

    int predv = 0;
    if (t < 64 && n >= 1024) {
        uint4 x = __ldg((const uint4*)term_raw + t);
        uint4 y = __ldg((const uint4*)trun_raw + t);
        predv = ((x.x | x.y | x.z | x.w | y.x | y.y | y.z | y.w) & 0xFFFFFF00u) != 0;
    }
    const int byteLayout = __syncthreads_or(predv);

    float accSum = 0.f, accSq = 0.f;
    const int tile = blockIdx.x * WARPS + wrp;

    if (tile < numTiles) {
        const long long tileStart = (long long)tile * TILE;
        const long long tileEnd   = tileStart + TILE;

        if (tileEnd <= (long long)n) {
            // ---------- fast path ----------
            // compact state: dd[16] + 16-bit done mask
            float dd[16];
            unsigned dmask = 0;
#pragma unroll
            for (int p = 0; p < NPASS; p++) {
                const long long b = tileStart + (long long)p * PASS + lane * 4;
                float4 rr = __ldg((const float4*)(rewards + b));
                float4 vv = __ldg((const float4*)(values + b));
                float4 nn = __ldg((const float4*)(next_values + b));
                int te[4], tu[4];
                if (byteLayout) {
                    unsigned tm = *(const unsigned*)((const uint8_t*)term_raw + b);
                    unsigned tr = *(const unsigned*)((const uint8_t*)trun_raw + b);
#pragma unroll
                    for (int j = 0; j < 4; j++) {
                        te[j] = (int)((tm >> (8 * j)) & 0xFFu);
                        tu[j] = (int)((tr >> (8 * j)) & 0xFFu);
                    }
                } else {
                    int4 a0 = __ldg((const int4*)((const int*)term_raw + b));
                    int4 b0 = __ldg((const int4*)((const int*)trun_raw + b));
                    te[0]=a0.x; te[1]=a0.y; te[2]=a0.z; te[3]=a0.w;
                    tu[0]=b0.x; tu[1]=b0.y; tu[2]=b0.z; tu[3]=b0.w;
                }
                float r4[4] = {rr.x, rr.y, rr.z, rr.w};
                float v4[4] = {vv.x, vv.y, vv.z, vv.w};
                float n4[4] = {nn.x, nn.y, nn.z, nn.w};
#pragma unroll
                for (int j = 0; j < 4; j++) {
                    bool b_te = te[j] != 0, b_tu = tu[j] != 0;
                    float nt = b_te ? 0.f : 1.f;
                    dd[p * 4 + j] = r4[j] + GAMMA_F * nt * n4[j] - v4[j];
                    if (b_te || b_tu) dmask |= 1u << (p * 4 + j);
                }
            }

            // halo -> seed
            float seed = 0.f;
            if (tileEnd < (long long)n) {
                float hcc[4], hdd[4];
                load_cd4_guard(tileEnd + lane * 4, n, byteLayout,
                               rewards, values, next_values, term_raw, trun_raw,
                               hcc, hdd);
                float hC = 1.f, hD = 0.f;
#pragma unroll
                for (int j = 3; j >= 0; j--) { hD = fmaf(hcc[j], hD, hdd[j]); hC *= hcc[j]; }
                warp_suffix_scan(hC, hD, lane);
                seed = __shfl_sync(0xFFFFFFFFu, hD, 0);
            }

            // passes right-to-left
#pragma unroll
            for (int p = NPASS - 1; p >= 0; p--) {
                const unsigned nib = (dmask >> (p * 4)) & 0xFu;
                float C = (nib == 0u) ? GL4 : 0.f;
                float D = 0.f;
#pragma unroll
                for (int j = 3; j >= 0; j--) {
                    float cj = (nib & (1u << j)) ? 0.f : GL;
                    D = fmaf(cj, D, dd[p * 4 + j]);
                }

                float iC = C, iD = D;
                warp_suffix_scan(iC, iD, lane);
                float eC = __shfl_down_sync(0xFFFFFFFFu, iC, 1);
                float eD = __shfl_down_sync(0xFFFFFFFFu, iD, 1);
                if (lane == 31) { eC = 1.f; eD = 0.f; }

                float x = fmaf(eC, seed, eD);
                float o0, o1, o2, o3;
                {
                    float c3 = (nib & 8u) ? 0.f : GL;
                    float c2 = (nib & 4u) ? 0.f : GL;
                    float c1 = (nib & 2u) ? 0.f : GL;
                    float c0 = (nib & 1u) ? 0.f : GL;
                    x = fmaf(c3, x, dd[p * 4 + 3]); o3 = x;
                    x = fmaf(c2, x, dd[p * 4 + 2]); o2 = x;
                    x = fmaf(c1, x, dd[p * 4 + 1]); o1 = x;
                    x = fmaf(c0, x, dd[p * 4 + 0]); o0 = x;
                }
                accSum += o0 + o1 + o2 + o3;
                accSq = fmaf(o0, o0, accSq); accSq = fmaf(o1, o1, accSq);
                accSq = fmaf(o2, o2, accSq); accSq = fmaf(o3, o3, accSq);

                *(float4*)(g_adv + tileStart + (long long)p * PASS + lane * 4) =
                    make_float4(o0, o1, o2, o3);

                float ns = fmaf(iC, seed, iD);
                seed = __shfl_sync(0xFFFFFFFFu, ns, 0);
            }
        } else {
            // ---------- tail tile (rare) ----------
            float seed = 0.f;
            for (int p = NPASS - 1; p >= 0; p--) {
                float cc[4], ddl[4];
                const long long b = tileStart + (long long)p * PASS + lane * 4;
                load_cd4_guard(b, n, byteLayout,
                               rewards, values, next_values, term_raw, trun_raw, cc, ddl);
                float C = 1.f, D = 0.f;
#pragma unroll
                for (int j = 3; j >= 0; j--) { D = fmaf(cc[j], D, ddl[j]); C *= cc[j]; }
                float iC = C, iD = D;
                warp_suffix_scan(iC, iD, lane);
                float eC = __shfl_down_sync(0xFFFFFFFFu, iC, 1);
                float eD = __shfl_down_sync(0xFFFFFFFFu, iD, 1);
                if (lane == 31) { eC = 1.f; eD = 0.f; }
                float x = fmaf(eC, seed, eD);
#pragma unroll
                for (int j = 3; j >= 0; j--) {
                    x = fmaf(cc[j], x, ddl[j]);
                    long long idx = b + j;
                    if (idx < (long long)n) {
                        g_adv[idx] = x;
                        accSum += x; accSq = fmaf(x, x, accSq);
                    }
                }
                float ns = fmaf(iC, seed, iD);
                seed = __shfl_sync(0xFFFFFFFFu, ns, 0);
            }
        }
    }

    // ---- block partial sums ----
    double ds = (double)accSum, dq = (double)accSq;
#pragma unroll
    for (int o = 16; o > 0; o >>= 1) {
        ds += __shfl_down_sync(0xFFFFFFFFu, ds, o);
        dq += __shfl_down_sync(0xFFFFFFFFu, dq, o);
    }
    if (lane == 0) { s_wsum[wrp] = ds; s_wsq[wrp] = dq; }
    __syncthreads();
    if (t == 0) {
        double ts = 0.0, tq = 0.0;
#pragma unroll
        for (int w = 0; w < WARPS; w++) { ts += s_wsum[w]; tq += s_wsq[w]; }
        g_psum[blockIdx.x] = ts;
        g_psq[blockIdx.x]  = tq;
    }
}

// ===== kernel B: stats =====
__global__ void stats_kernel(int numBlocks, int n) {
    __shared__ double s_wsum[8];
    __shared__ double s_wsq[8];
    const int t = threadIdx.x;
    const int lane = t & 31, wrp = t >> 5;
    double ds = 0.0, dq = 0.0;
    for (int i = t; i < numBlocks; i += 256) { ds += g_psum[i]; dq += g_psq[i]; }
#pragma unroll
    for (int o = 16; o > 0; o >>= 1) {
        ds += __shfl_down_sync(0xFFFFFFFFu, ds, o);
        dq += __shfl_down_sync(0xFFFFFFFFu, dq, o);
    }
    if (lane == 0) { s_wsum[wrp] = ds; s_wsq[wrp] = dq; }
    __syncthreads();
    if (t == 0) {
        double ts = 0.0, tq = 0.0;
#pragma unroll
        for (int w = 0; w < 8; w++) { ts += s_wsum[w]; tq += s_wsq[w]; }
        double mean = ts / (double)n;
        double var = (tq - ts * ts / (double)n) / (double)(n - 1);
        if (var < 0.0) var = 0.0;
        g_mean = (float)mean;
        g_rinv = (float)(1.0 / (sqrt(var) + 1e-9));
    }
}

__device__ __forceinline__ void ppo_row(float a, float v, float lp, float olp,
                                        float mean, float rinv, float* o) {
    float an = (a - mean) * rinv;
    float lr = a + v;
    float ratio = __expf(lp - olp);
    float cl = fminf(fmaxf(ratio, 1.f - CLIP_EPS_F), 1.f + CLIP_EPS_F);
    float loss = -fminf(ratio * an, cl * an);
    o[0] = an; o[1] = lr; o[2] = loss;
}

// ===== kernel C: epilogue (smem-staged coalesced output) =====
__global__ __launch_bounds__(BLOCK)
void output_kernel(const float* __restrict__ values,
                   const float* __restrict__ log_probs,
                   const float* __restrict__ old_log_probs,
                   float* __restrict__ out, int n)
{
    __shared__ float4 s4[3 * BLOCK];
    const float mean = g_mean, rinv = g_rinv;
    const int t = threadIdx.x;
    const long long blockBase = (long long)blockIdx.x * (BLOCK * 4);
    const long long b4 = blockBase + t * 4;

    if (blockBase + BLOCK * 4 <= (long long)n) {
        float4 a   = *(const float4*)(g_adv + b4);
        float4 v   = __ldg((const float4*)(values + b4));
        float4 lp  = __ldg((const float4*)(log_probs + b4));
        float4 olp = __ldg((const float4*)(old_log_probs + b4));
        float o[12];
        ppo_row(a.x, v.x, lp.x, olp.x, mean, rinv, o + 0);
        ppo_row(a.y, v.y, lp.y, olp.y, mean, rinv, o + 3);
        ppo_row(a.z, v.z, lp.z, olp.z, mean, rinv, o + 6);
        ppo_row(a.w, v.w, lp.w, olp.w, mean, rinv, o + 9);
        s4[3 * t + 0] = make_float4(o[0], o[1], o[2],  o[3]);
        s4[3 * t + 1] = make_float4(o[4], o[5], o[6],  o[7]);
        s4[3 * t + 2] = make_float4(o[8], o[9], o[10], o[11]);
        __syncthreads();
        float4* dst = (float4*)(out + blockBase * 3);
        __stcs(dst + t,             s4[t]);
        __stcs(dst + t + BLOCK,     s4[t + BLOCK]);
        __stcs(dst + t + 2 * BLOCK, s4[t + 2 * BLOCK]);
    } else {
        for (long long i = b4; i < b4 + 4 && i < (long long)n; i++) {
            float o[3];
            ppo_row(g_adv[i], values[i], log_probs[i], old_log_probs[i], mean, rinv, o);
            out[i * 3 + 0] = o[0];
            out[i * 3 + 1] = o[1];
            out[i * 3 + 2] = o[2];
        }
    }
}

extern "C" void kernel_launch(void* const* d_in, const int* in_sizes, int n_in,
                              void* d_out, int out_size) {
    const float* rewards       = (const float*)d_in[0];
    const float* values        = (const float*)d_in[1];
    const float* next_values   = (const float*)d_in[2];
    const float* log_probs     = (const float*)d_in[3];
    const float* old_log_probs = (const float*)d_in[4];
    const void*  terminated    = d_in[5];
    const void*  truncated     = d_in[6];
    float* out = (float*)d_out;

    int n = in_sizes[0];
    int numTiles = (n + TILE - 1) / TILE;
    int gridA = (numTiles + WARPS - 1) / WARPS;
    if (gridA > MAXBLK) gridA = MAXBLK;
    int gridC = (int)(((long long)n + BLOCK * 4 - 1) / (BLOCK * 4));

    scan_kernel<<<gridA, BLOCK>>>(rewards, values, next_values,
                                  terminated, truncated, n, numTiles);
    stats_kernel<<<1, 256>>>(gridA, n);
    output_kernel<<<gridC, BLOCK>>>(values, log_probs, old_log_probs, out, n);
}